// round 7
// baseline (speedup 1.0000x reference)
#include <cuda_runtime.h>
#include <cuda_bf16.h>

// Shape (fixed): words (32, 4096, 768) f32, diff (32,4096) [unused],
// W (1,1536) f32, b (1,) f32 -> out (32,1) f32.
#define B 32
#define L 4096
#define H 768
#define TWOH 1536
#define NEGV (-1e30f)

// Chunking: each block owns R rows of one batch.
#define CHUNKS 64               // chunks (blocks) per batch
#define R (L / CHUNKS)          // 64 rows per chunk
#define NCHUNK (B * CHUNKS)     // 2048 blocks

// Per-chunk exports + per-batch tickets (padded: one counter per 128B line
// to avoid L2-slice pairing between adjacent counters).
__device__ float g_cmax[NCHUNK];
__device__ float g_stail[NCHUNK * 5];
__device__ float g_thead[NCHUNK * 5];
__device__ unsigned int g_cnt[B * 32];   // use index b*32

// ---------------------------------------------------------------------------
// Single kernel, per-batch ticket:
//   all blocks: s/t projections (warp-per-row, float4 streaming, regs<=32),
//     internal windowed max, boundary exports, atomicAdd on OWN batch counter.
//   the 64th block of each batch finishes THAT batch: 64 chunk maxes +
//     63 boundaries + bias/relu -> out[b]. 31/32 finishers overlap other
//     batches' main work; only the last is exposed (~1us).
// Boundary pairs chunk c -> c+1: l=R-5+i, l+k=R+j, k=5-i+j in [1,5] <=> j<=i.
// ---------------------------------------------------------------------------
__global__ __launch_bounds__(256) void ww_fused_kernel(
    const float* __restrict__ words,
    const float* __restrict__ W,
    const float* __restrict__ bias,
    float* __restrict__ out)
{
    __shared__ float sw[TWOH];       // w1 | w2
    __shared__ float s_sh[R];
    __shared__ float t_sh[R];
    __shared__ float red[8];
    __shared__ unsigned int s_last;

    for (int i = threadIdx.x; i < TWOH; i += blockDim.x) sw[i] = W[i];
    __syncthreads();

    const float4* w1v = reinterpret_cast<const float4*>(sw);
    const float4* w2v = reinterpret_cast<const float4*>(sw + H);

    const int c    = blockIdx.x;          // chunk id, 0..NCHUNK-1
    const int b    = c / CHUNKS;
    const int ch   = c % CHUNKS;
    const int row0 = b * L + ch * R;

    const int warp = threadIdx.x >> 5;
    const int lane = threadIdx.x & 31;

    // 8 warps x 8 rows each: one contiguous 3KB stream per warp, regs <= 32.
    for (int r = warp; r < R; r += 8) {
        const float4* wp = reinterpret_cast<const float4*>(
            words + (size_t)(row0 + r) * H);
        float s = 0.f, t = 0.f;
#pragma unroll
        for (int i = 0; i < H / 128; i++) {        // 6 steps, 512B/warp/step
            const int idx = lane + i * 32;
            const float4 v  = __ldcs(wp + idx);    // read-once streaming
            const float4 a  = w1v[idx];
            const float4 b2 = w2v[idx];
            s = fmaf(v.x, a.x,  fmaf(v.y, a.y,  fmaf(v.z, a.z,  fmaf(v.w, a.w,  s))));
            t = fmaf(v.x, b2.x, fmaf(v.y, b2.y, fmaf(v.z, b2.z, fmaf(v.w, b2.w, t))));
        }
#pragma unroll
        for (int off = 16; off > 0; off >>= 1) {
            s += __shfl_xor_sync(0xFFFFFFFFu, s, off);
            t += __shfl_xor_sync(0xFFFFFFFFu, t, off);
        }
        if (lane == 0) {
            s_sh[r] = s;
            t_sh[r] = t;
        }
    }
    __syncthreads();

    // Internal windowed max: threads 0..R-1 each take one l.
    float m = NEGV;
    if (threadIdx.x < R) {
        const int l = threadIdx.x;
        const float sl = s_sh[l];
#pragma unroll
        for (int k = 1; k <= 5; k++)
            if (l + k < R) m = fmaxf(m, sl + t_sh[l + k]);
    }
#pragma unroll
    for (int off = 16; off > 0; off >>= 1)
        m = fmaxf(m, __shfl_xor_sync(0xFFFFFFFFu, m, off));
    if (lane == 0) red[warp] = m;
    __syncthreads();
    if (threadIdx.x == 0) {
        float mm = red[0];
#pragma unroll
        for (int w = 1; w < 8; w++) mm = fmaxf(mm, red[w]);
        g_cmax[c] = mm;
    }
    if (threadIdx.x < 5) {
        g_thead[c * 5 + threadIdx.x] = t_sh[threadIdx.x];
        g_stail[c * 5 + threadIdx.x] = s_sh[R - 5 + threadIdx.x];
    }
    __syncthreads();

    // --- per-batch ticket: last block of THIS batch finishes the batch ---
    if (threadIdx.x == 0) {
        __threadfence();                          // release exports
        s_last = atomicAdd(&g_cnt[b * 32], 1u);
    }
    __syncthreads();
    if (s_last != CHUNKS - 1) return;
    __threadfence();                              // acquire all batch exports

    // Finish batch b: threads 0..63 chunk maxes, 64..126 boundaries.
    {
        const int t  = threadIdx.x;
        const int c0 = b * CHUNKS;
        float fm = NEGV;
        if (t < CHUNKS) {
            fm = g_cmax[c0 + t];
        } else if (t >= 64 && t < 64 + CHUNKS - 1) {
            const int cc = c0 + (t - 64);
            float st[5], th[5];
#pragma unroll
            for (int i = 0; i < 5; i++) st[i] = g_stail[cc * 5 + i];
#pragma unroll
            for (int j = 0; j < 5; j++) th[j] = g_thead[(cc + 1) * 5 + j];
#pragma unroll
            for (int i = 0; i < 5; i++)
#pragma unroll
                for (int j = 0; j < 5; j++)
                    if (j <= i) fm = fmaxf(fm, st[i] + th[j]);
        }
#pragma unroll
        for (int off = 16; off > 0; off >>= 1)
            fm = fmaxf(fm, __shfl_xor_sync(0xFFFFFFFFu, fm, off));
        if ((t & 31) == 0) red[t >> 5] = fm;
        __syncthreads();
        if (t == 0) {
            float mm = red[0];
#pragma unroll
            for (int w = 1; w < 8; w++) mm = fmaxf(mm, red[w]);
            out[b] = fmaxf(0.0f, mm + bias[0]);
            g_cnt[b * 32] = 0;                    // reset for next replay
        }
    }
}

extern "C" void kernel_launch(void* const* d_in, const int* in_sizes, int n_in,
                              void* d_out, int out_size)
{
    const float* words = (const float*)d_in[0];
    // d_in[1] = diff : unused by the reference computation
    const float* W     = (const float*)d_in[2];
    const float* bias  = (const float*)d_in[3];
    float* out         = (float*)d_out;

    ww_fused_kernel<<<NCHUNK, 256>>>(words, W, bias, out);
}

// round 8
// speedup vs baseline: 1.0066x; 1.0066x over previous
#include <cuda_runtime.h>
#include <cuda_bf16.h>
#include <cooperative_groups.h>

// Shape (fixed): words (32, 4096, 768) f32, diff (32,4096) [unused],
// W (1,1536) f32, b (1,) f32 -> out (32,1) f32.
#define B 32
#define L 4096
#define H 768
#define TWOH 1536
#define NEGV (-1e30f)

// Chunking: each block owns R rows of one batch.
#define CHUNKS 64               // chunks per batch
#define R (L / CHUNKS)          // 64 rows per chunk
#define NCHUNK (B * CHUNKS)     // 2048 blocks

// Per-chunk exports.
__device__ float g_cmax[NCHUNK];
__device__ float g_stail[NCHUNK * 5];
__device__ float g_thead[NCHUNK * 5];

// ---------------------------------------------------------------------------
// Kernel 1 (hot, pure: no atomics/fences — they cost ~5us of DRAM throughput,
// measured R5/R7): s/t projections (warp-per-row, float4 streaming, regs<=32),
// internal windowed max, boundary exports.
// ---------------------------------------------------------------------------
__global__ __launch_bounds__(256) void ww_fused_kernel(
    const float* __restrict__ words,
    const float* __restrict__ W)
{
    __shared__ float sw[TWOH];       // w1 | w2
    __shared__ float s_sh[R];
    __shared__ float t_sh[R];
    __shared__ float red[8];

    for (int i = threadIdx.x; i < TWOH; i += blockDim.x) sw[i] = W[i];
    __syncthreads();

    const float4* w1v = reinterpret_cast<const float4*>(sw);
    const float4* w2v = reinterpret_cast<const float4*>(sw + H);

    const int c    = blockIdx.x;          // chunk id, 0..NCHUNK-1
    const int b    = c / CHUNKS;
    const int ch   = c % CHUNKS;
    const int row0 = b * L + ch * R;

    const int warp = threadIdx.x >> 5;
    const int lane = threadIdx.x & 31;

    // 8 warps x 8 rows each: one contiguous 3KB stream per warp, regs <= 32.
    for (int r = warp; r < R; r += 8) {
        const float4* wp = reinterpret_cast<const float4*>(
            words + (size_t)(row0 + r) * H);
        float s = 0.f, t = 0.f;
#pragma unroll
        for (int i = 0; i < H / 128; i++) {        // 6 steps, 512B/warp/step
            const int idx = lane + i * 32;
            const float4 v  = __ldcs(wp + idx);    // read-once streaming
            const float4 a  = w1v[idx];
            const float4 b2 = w2v[idx];
            s = fmaf(v.x, a.x,  fmaf(v.y, a.y,  fmaf(v.z, a.z,  fmaf(v.w, a.w,  s))));
            t = fmaf(v.x, b2.x, fmaf(v.y, b2.y, fmaf(v.z, b2.z, fmaf(v.w, b2.w, t))));
        }
#pragma unroll
        for (int off = 16; off > 0; off >>= 1) {
            s += __shfl_xor_sync(0xFFFFFFFFu, s, off);
            t += __shfl_xor_sync(0xFFFFFFFFu, t, off);
        }
        if (lane == 0) {
            s_sh[r] = s;
            t_sh[r] = t;
        }
    }
    __syncthreads();

    // Internal windowed max: threads 0..R-1 each take one l.
    float m = NEGV;
    if (threadIdx.x < R) {
        const int l = threadIdx.x;
        const float sl = s_sh[l];
#pragma unroll
        for (int k = 1; k <= 5; k++)
            if (l + k < R) m = fmaxf(m, sl + t_sh[l + k]);
    }
#pragma unroll
    for (int off = 16; off > 0; off >>= 1)
        m = fmaxf(m, __shfl_xor_sync(0xFFFFFFFFu, m, off));
    if (lane == 0) red[warp] = m;
    __syncthreads();
    if (threadIdx.x == 0) {
        float mm = red[0];
#pragma unroll
        for (int w = 1; w < 8; w++) mm = fmaxf(mm, red[w]);
        g_cmax[c] = mm;
    }
    if (threadIdx.x < 5) {
        g_thead[c * 5 + threadIdx.x] = t_sh[threadIdx.x];
        g_stail[c * 5 + threadIdx.x] = s_sh[R - 5 + threadIdx.x];
    }
}

// ---------------------------------------------------------------------------
// Kernel 2 (finisher, PDL): launches overlapped with kernel 1 via
// programmatic dependent launch; blocks park in griddepsync and proceed the
// instant kernel 1 completes+flushes. One block per batch, 128 threads:
//   threads 0..63   : chunk maxes
//   threads 64..126 : one boundary each (15 pairs; MLP=10 L2-resident loads)
// Boundary pairs chunk c -> c+1: l=R-5+i, l+k=R+j, k=5-i+j in [1,5] <=> j<=i.
// ---------------------------------------------------------------------------
__global__ __launch_bounds__(128) void ww_final_kernel(
    const float* __restrict__ bias,
    float* __restrict__ out)
{
    cudaGridDependencySynchronize();   // wait for main kernel's writes

    __shared__ float red[4];
    const int b  = blockIdx.x;
    const int t  = threadIdx.x;
    const int c0 = b * CHUNKS;

    float m = NEGV;
    if (t < CHUNKS) {
        m = g_cmax[c0 + t];
    } else if (t < 64 + CHUNKS - 1) {
        const int c = c0 + (t - 64);
        float st[5], th[5];
#pragma unroll
        for (int i = 0; i < 5; i++) st[i] = g_stail[c * 5 + i];
#pragma unroll
        for (int j = 0; j < 5; j++) th[j] = g_thead[(c + 1) * 5 + j];
#pragma unroll
        for (int i = 0; i < 5; i++)
#pragma unroll
            for (int j = 0; j < 5; j++)
                if (j <= i) m = fmaxf(m, st[i] + th[j]);
    }

#pragma unroll
    for (int off = 16; off > 0; off >>= 1)
        m = fmaxf(m, __shfl_xor_sync(0xFFFFFFFFu, m, off));
    if ((t & 31) == 0) red[t >> 5] = m;
    __syncthreads();
    if (t == 0) {
        float mm = fmaxf(fmaxf(red[0], red[1]), fmaxf(red[2], red[3]));
        out[b] = fmaxf(0.0f, mm + bias[0]);
    }
}

extern "C" void kernel_launch(void* const* d_in, const int* in_sizes, int n_in,
                              void* d_out, int out_size)
{
    const float* words = (const float*)d_in[0];
    // d_in[1] = diff : unused by the reference computation
    const float* W     = (const float*)d_in[2];
    const float* bias  = (const float*)d_in[3];
    float* out         = (float*)d_out;

    ww_fused_kernel<<<NCHUNK, 256>>>(words, W);

    // Finisher with programmatic dependent launch: grid setup overlaps the
    // main kernel; griddepsync inside provides the ordering + visibility.
    cudaLaunchConfig_t cfg = {};
    cfg.gridDim  = dim3(B, 1, 1);
    cfg.blockDim = dim3(128, 1, 1);
    cfg.dynamicSmemBytes = 0;
    cfg.stream = 0;
    cudaLaunchAttribute attr[1];
    attr[0].id = cudaLaunchAttributeProgrammaticStreamSerialization;
    attr[0].val.programmaticStreamSerializationAllowed = 1;
    cfg.attrs = attr;
    cfg.numAttrs = 1;
    cudaLaunchKernelEx(&cfg, ww_final_kernel, bias, out);
}

// round 9
// speedup vs baseline: 1.0370x; 1.0302x over previous
#include <cuda_runtime.h>
#include <cuda_bf16.h>
#include <cooperative_groups.h>

// Shape (fixed): words (32, 4096, 768) f32, diff (32,4096) [unused],
// W (1,1536) f32, b (1,) f32 -> out (32,1) f32.
#define B 32
#define L 4096
#define H 768
#define TWOH 1536
#define NEGV (-1e30f)

// Chunking: each block owns R rows of one batch.
#define CHUNKS 64               // chunks per batch
#define R (L / CHUNKS)          // 64 rows per chunk
#define NCHUNK (B * CHUNKS)     // 2048 blocks

// Per-chunk exports.
__device__ float g_cmax[NCHUNK];
__device__ float g_stail[NCHUNK * 5];
__device__ float g_thead[NCHUNK * 5];

// ---------------------------------------------------------------------------
// Kernel 1 (hot, pure: no atomics/fences): s/t projections, internal windowed
// max, boundary exports. Warp->row map is CONTIGUOUS: warp w owns rows
// [8w, 8w+8), so each warp's global loads form one linear 24KB stream
// (vs 24KB jumps every 3KB with the old strided map) -> better HBM row
// locality at identical coalescing/regs/occupancy.
// ---------------------------------------------------------------------------
__global__ __launch_bounds__(256) void ww_fused_kernel(
    const float* __restrict__ words,
    const float* __restrict__ W)
{
    __shared__ float sw[TWOH];       // w1 | w2
    __shared__ float s_sh[R];
    __shared__ float t_sh[R];
    __shared__ float red[8];

    for (int i = threadIdx.x; i < TWOH; i += blockDim.x) sw[i] = W[i];
    __syncthreads();

    const float4* w1v = reinterpret_cast<const float4*>(sw);
    const float4* w2v = reinterpret_cast<const float4*>(sw + H);

    const int c    = blockIdx.x;          // chunk id, 0..NCHUNK-1
    const int b    = c / CHUNKS;
    const int ch   = c % CHUNKS;
    const int row0 = b * L + ch * R;

    const int warp = threadIdx.x >> 5;
    const int lane = threadIdx.x & 31;

    // 8 warps x 8 CONSECUTIVE rows each: linear 24KB stream per warp.
    const float4* wp = reinterpret_cast<const float4*>(
        words + (size_t)(row0 + warp * 8) * H);
    for (int it = 0; it < 8; it++) {
        const int r = warp * 8 + it;
        float s = 0.f, t = 0.f;
#pragma unroll
        for (int i = 0; i < H / 128; i++) {        // 6 steps, 512B/warp/step
            const int idx = lane + i * 32;
            const float4 v  = __ldcs(wp + idx);    // read-once streaming
            const float4 a  = w1v[idx];
            const float4 b2 = w2v[idx];
            s = fmaf(v.x, a.x,  fmaf(v.y, a.y,  fmaf(v.z, a.z,  fmaf(v.w, a.w,  s))));
            t = fmaf(v.x, b2.x, fmaf(v.y, b2.y, fmaf(v.z, b2.z, fmaf(v.w, b2.w, t))));
        }
#pragma unroll
        for (int off = 16; off > 0; off >>= 1) {
            s += __shfl_xor_sync(0xFFFFFFFFu, s, off);
            t += __shfl_xor_sync(0xFFFFFFFFu, t, off);
        }
        if (lane == 0) {
            s_sh[r] = s;
            t_sh[r] = t;
        }
        wp += H / 4;                               // advance one row (3KB)
    }
    __syncthreads();

    // Internal windowed max: threads 0..R-1 each take one l.
    float m = NEGV;
    if (threadIdx.x < R) {
        const int l = threadIdx.x;
        const float sl = s_sh[l];
#pragma unroll
        for (int k = 1; k <= 5; k++)
            if (l + k < R) m = fmaxf(m, sl + t_sh[l + k]);
    }
#pragma unroll
    for (int off = 16; off > 0; off >>= 1)
        m = fmaxf(m, __shfl_xor_sync(0xFFFFFFFFu, m, off));
    if (lane == 0) red[warp] = m;
    __syncthreads();
    if (threadIdx.x == 0) {
        float mm = red[0];
#pragma unroll
        for (int w = 1; w < 8; w++) mm = fmaxf(mm, red[w]);
        g_cmax[c] = mm;
    }
    if (threadIdx.x < 5) {
        g_thead[c * 5 + threadIdx.x] = t_sh[threadIdx.x];
        g_stail[c * 5 + threadIdx.x] = s_sh[R - 5 + threadIdx.x];
    }
}

// ---------------------------------------------------------------------------
// Kernel 2 (finisher, PDL): one block per batch, 128 threads.
//   threads 0..63   : chunk maxes
//   threads 64..126 : one boundary each (15 pairs; MLP=10 L2-resident loads)
// Boundary pairs chunk c -> c+1: l=R-5+i, l+k=R+j, k=5-i+j in [1,5] <=> j<=i.
// ---------------------------------------------------------------------------
__global__ __launch_bounds__(128) void ww_final_kernel(
    const float* __restrict__ bias,
    float* __restrict__ out)
{
    cudaGridDependencySynchronize();   // wait for main kernel's writes

    __shared__ float red[4];
    const int b  = blockIdx.x;
    const int t  = threadIdx.x;
    const int c0 = b * CHUNKS;

    float m = NEGV;
    if (t < CHUNKS) {
        m = g_cmax[c0 + t];
    } else if (t < 64 + CHUNKS - 1) {
        const int c = c0 + (t - 64);
        float st[5], th[5];
#pragma unroll
        for (int i = 0; i < 5; i++) st[i] = g_stail[c * 5 + i];
#pragma unroll
        for (int j = 0; j < 5; j++) th[j] = g_thead[(c + 1) * 5 + j];
#pragma unroll
        for (int i = 0; i < 5; i++)
#pragma unroll
            for (int j = 0; j < 5; j++)
                if (j <= i) m = fmaxf(m, st[i] + th[j]);
    }

#pragma unroll
    for (int off = 16; off > 0; off >>= 1)
        m = fmaxf(m, __shfl_xor_sync(0xFFFFFFFFu, m, off));
    if ((t & 31) == 0) red[t >> 5] = m;
    __syncthreads();
    if (t == 0) {
        float mm = fmaxf(fmaxf(red[0], red[1]), fmaxf(red[2], red[3]));
        out[b] = fmaxf(0.0f, mm + bias[0]);
    }
}

extern "C" void kernel_launch(void* const* d_in, const int* in_sizes, int n_in,
                              void* d_out, int out_size)
{
    const float* words = (const float*)d_in[0];
    // d_in[1] = diff : unused by the reference computation
    const float* W     = (const float*)d_in[2];
    const float* bias  = (const float*)d_in[3];
    float* out         = (float*)d_out;

    ww_fused_kernel<<<NCHUNK, 256>>>(words, W);

    // Finisher with programmatic dependent launch.
    cudaLaunchConfig_t cfg = {};
    cfg.gridDim  = dim3(B, 1, 1);
    cfg.blockDim = dim3(128, 1, 1);
    cfg.dynamicSmemBytes = 0;
    cfg.stream = 0;
    cudaLaunchAttribute attr[1];
    attr[0].id = cudaLaunchAttributeProgrammaticStreamSerialization;
    attr[0].val.programmaticStreamSerializationAllowed = 1;
    cfg.attrs = attr;
    cfg.numAttrs = 1;
    cudaLaunchKernelEx(&cfg, ww_final_kernel, bias, out);
}